// round 3
// baseline (speedup 1.0000x reference)
#include <cuda_runtime.h>
#include <cstdint>
#include <cstddef>

// ---------------- problem dims ----------------
#define A_DIM 4
#define M_DIM 1024
#define H_DIM 1024
#define E_DIM 8
#define N_DIM 4096

// ---------------- tile config ----------------
#define BM 128
#define BN 128
#define BK 32
#define NSTAGE 4
// padded smem strides (floats) for conflict-free fragment LDS
#define LDA_S 36     /* A tile row stride: bank=(4g+q)%32 distinct     */
#define LDB_S 136    /* B tile row stride: bank=(8q+g)%32 distinct     */
#define A_STG_FLOATS (BM * LDA_S)          /* 4608  */
#define B_STG_FLOATS (BK * LDB_S)          /* 4352  */
#define STG_FLOATS   (A_STG_FLOATS + B_STG_FLOATS)   /* 8960 = 35840 B */
#define SMEM_DYN     (NSTAGE * STG_FLOATS * 4)       /* 143360 B       */

// ---------------- device scratch ----------------
__device__ float g_part[(size_t)E_DIM * H_DIM * H_DIM];  // 32 MB per-expert partial W
__device__ float g_wsum[(size_t)H_DIM * H_DIM];          // 4 MB  combined W

// ---------------- helpers ----------------
__device__ __forceinline__ uint32_t smem_u32(const void* p) {
    uint32_t a;
    asm("{ .reg .u64 t; cvta.to.shared.u64 t, %1; cvt.u32.u64 %0, t; }" : "=r"(a) : "l"(p));
    return a;
}
__device__ __forceinline__ uint32_t f2tf32(float f) {   // round-to-nearest tf32
    uint32_t u;
    asm("cvt.rna.tf32.f32 %0, %1;" : "=r"(u) : "f"(f));
    return u;
}
__device__ __forceinline__ void cp16(uint32_t dst, const float* src) {
    asm volatile("cp.async.cg.shared.global [%0], [%1], 16;\n"
                 :: "r"(dst), "l"(__cvta_generic_to_global(src)) : "memory");
}
__device__ __forceinline__ void cp_commit() {
    asm volatile("cp.async.commit_group;\n" ::: "memory");
}
__device__ __forceinline__ void mma_tf32(float* c, const uint32_t* a, const uint32_t* b) {
    asm volatile(
        "mma.sync.aligned.m16n8k8.row.col.f32.tf32.tf32.f32 "
        "{%0,%1,%2,%3}, {%4,%5,%6,%7}, {%8,%9}, {%0,%1,%2,%3};"
        : "+f"(c[0]), "+f"(c[1]), "+f"(c[2]), "+f"(c[3])
        : "r"(a[0]), "r"(a[1]), "r"(a[2]), "r"(a[3]), "r"(b[0]), "r"(b[1]));
}

// =============================================================================
// Generic tf32 GEMM: C[BM x BN] = A[M x K](row-major, lda) * B[K x N](row-major, ldb)
// Operands rounded to tf32 in-register (rna). C written fp32 (plain store).
// Grid: x = n-tile, y = m-tile, z = batch (resolved by caller lambda-style ptr math).
// =============================================================================
template <int KB>   // number of BK-blocks in K
__global__ void __launch_bounds__(256, 1)
gemm_tf32_ker(const float* __restrict__ Ag, const float* __restrict__ Bg,
              float* __restrict__ Cg,
              int lda, int ldb, int ldc,
              size_t a_batch_stride, size_t b_batch_stride, size_t c_batch_stride) {
    extern __shared__ float sm[];

    const int tid  = threadIdx.x;
    const int lane = tid & 31;
    const int warp = tid >> 5;
    const int g = lane >> 2;          // group id 0..7
    const int q = lane & 3;           // thread-in-group 0..3
    const int wm = warp & 3;          // warp m index (4)
    const int wn = warp >> 2;         // warp n index (2)

    const int bz = blockIdx.z;
    const float* A = Ag + (size_t)bz * a_batch_stride + (size_t)blockIdx.y * BM * lda;
    const float* B = Bg + (size_t)bz * b_batch_stride + (size_t)blockIdx.x * BN;
    float*       C = Cg + (size_t)bz * c_batch_stride
                        + (size_t)blockIdx.y * BM * ldc + (size_t)blockIdx.x * BN;

    const uint32_t smem0 = smem_u32(sm);

    // ---- gmem -> smem load geometry (16B chunks) ----
    // A tile: 128 rows x 32 floats (8 chunks/row). thread covers chunk tid + 256*i.
    const int ar  = tid >> 3;          // base row (0..31), +32*i
    const int ac  = (tid & 7) * 4;     // float col
    // B tile: 32 rows x 128 floats (32 chunks/row).
    const int br  = tid >> 5;          // base row (0..7), +8*i
    const int bc  = (tid & 31) * 4;

    auto load_stage = [&](int slot, int kb) {
        uint32_t sa = smem0 + (uint32_t)slot * (STG_FLOATS * 4);
        uint32_t sb = sa + A_STG_FLOATS * 4;
        const float* Ak = A + (size_t)kb * BK;
        const float* Bk = B + (size_t)kb * BK * ldb;
        #pragma unroll
        for (int i = 0; i < 4; i++) {
            int r = ar + 32 * i;
            cp16(sa + (uint32_t)(r * LDA_S + ac) * 4u, Ak + (size_t)r * lda + ac);
        }
        #pragma unroll
        for (int i = 0; i < 4; i++) {
            int r = br + 8 * i;
            cp16(sb + (uint32_t)(r * LDB_S + bc) * 4u, Bk + (size_t)r * ldb + bc);
        }
        cp_commit();
    };

    // ---- accumulators ----
    float c[2][8][4];
    #pragma unroll
    for (int mt = 0; mt < 2; mt++)
        #pragma unroll
        for (int nt = 0; nt < 8; nt++)
            #pragma unroll
            for (int i = 0; i < 4; i++) c[mt][nt][i] = 0.0f;

    // ---- prologue ----
    #pragma unroll
    for (int s = 0; s < NSTAGE - 1; s++) load_stage(s, s);

    // ---- main loop ----
    #pragma unroll 1
    for (int kb = 0; kb < KB; ++kb) {
        asm volatile("cp.async.wait_group %0;\n" :: "n"(NSTAGE - 2) : "memory");
        __syncthreads();

        int pf = kb + NSTAGE - 1;
        if (pf < KB) load_stage(pf & (NSTAGE - 1), pf);
        else         cp_commit();   // keep group count aligned

        const float* As = sm + (kb & (NSTAGE - 1)) * STG_FLOATS;
        const float* Bs = As + A_STG_FLOATS;

        #pragma unroll
        for (int ks = 0; ks < 4; ks++) {
            // A fragments: 2 m-tiles
            uint32_t afr[2][4];
            #pragma unroll
            for (int mt = 0; mt < 2; mt++) {
                int r0 = wm * 32 + mt * 16 + g;
                int c0 = ks * 8 + q;
                afr[mt][0] = f2tf32(As[r0 * LDA_S + c0]);
                afr[mt][1] = f2tf32(As[(r0 + 8) * LDA_S + c0]);
                afr[mt][2] = f2tf32(As[r0 * LDA_S + c0 + 4]);
                afr[mt][3] = f2tf32(As[(r0 + 8) * LDA_S + c0 + 4]);
            }
            // B fragments: 8 n-tiles
            uint32_t bfr[8][2];
            #pragma unroll
            for (int nt = 0; nt < 8; nt++) {
                int col = wn * 64 + nt * 8 + g;
                int r0 = ks * 8 + q;
                bfr[nt][0] = f2tf32(Bs[r0 * LDB_S + col]);
                bfr[nt][1] = f2tf32(Bs[(r0 + 4) * LDB_S + col]);
            }
            #pragma unroll
            for (int mt = 0; mt < 2; mt++)
                #pragma unroll
                for (int nt = 0; nt < 8; nt++)
                    mma_tf32(c[mt][nt], afr[mt], bfr[nt]);
        }
    }

    // ---- epilogue: fp32 stores (float2 per fragment row) ----
    #pragma unroll
    for (int mt = 0; mt < 2; mt++) {
        #pragma unroll
        for (int nt = 0; nt < 8; nt++) {
            int r0  = wm * 32 + mt * 16 + g;
            int col = wn * 64 + nt * 8 + 2 * q;
            float2 v0 = make_float2(c[mt][nt][0], c[mt][nt][1]);
            float2 v1 = make_float2(c[mt][nt][2], c[mt][nt][3]);
            *reinterpret_cast<float2*>(C + (size_t)r0 * ldc + col)       = v0;
            *reinterpret_cast<float2*>(C + (size_t)(r0 + 8) * ldc + col) = v1;
        }
    }
}

// ---- reduce 8 expert partials into g_wsum (deterministic fixed order) ----
__global__ void reduce_experts_ker() {
    size_t i = (size_t)blockIdx.x * blockDim.x + threadIdx.x;  // over 1M/4 float4
    const float4* p = reinterpret_cast<const float4*>(g_part);
    float4 acc = p[i];
    #pragma unroll
    for (int e = 1; e < E_DIM; e++) {
        float4 v = p[(size_t)e * (H_DIM * H_DIM / 4) + i];
        acc.x += v.x; acc.y += v.y; acc.z += v.z; acc.w += v.w;
    }
    reinterpret_cast<float4*>(g_wsum)[i] = acc;
}

// ================= launch =================
extern "C" void kernel_launch(void* const* d_in, const int* in_sizes, int n_in,
                              void* d_out, int out_size) {
    const float* x  = (const float*)d_in[0];
    const float* w1 = (const float*)d_in[1];   // [E][H][N]
    const float* w2 = (const float*)d_in[2];   // [E][N][H]
    float* out = (float*)d_out;                // [A][M][H]

    float* part = nullptr; cudaGetSymbolAddress((void**)&part, g_part);
    float* wsum = nullptr; cudaGetSymbolAddress((void**)&wsum, g_wsum);

    cudaFuncSetAttribute(gemm_tf32_ker<N_DIM / BK>,
                         cudaFuncAttributeMaxDynamicSharedMemorySize, SMEM_DYN);
    cudaFuncSetAttribute(gemm_tf32_ker<H_DIM / BK>,
                         cudaFuncAttributeMaxDynamicSharedMemorySize, SMEM_DYN);

    // 1) per-expert combine: g_part[e] = w1[e] @ w2[e]
    //    A = w1[e]: [H x N] lda=N ; B = w2[e]: [N x H] ldb=H ; C: [H x H] ldc=H
    gemm_tf32_ker<N_DIM / BK>
        <<<dim3(H_DIM / BN, H_DIM / BM, E_DIM), 256, SMEM_DYN>>>(
            w1, w2, part,
            N_DIM, H_DIM, H_DIM,
            (size_t)H_DIM * N_DIM, (size_t)N_DIM * H_DIM, (size_t)H_DIM * H_DIM);

    // 2) reduce experts: g_wsum = sum_e g_part[e]
    reduce_experts_ker<<<(H_DIM * H_DIM / 4) / 256, 256>>>();

    // 3) apply: out = x @ W   (x as [A*M x H], single batch)
    gemm_tf32_ker<H_DIM / BK>
        <<<dim3(H_DIM / BN, (A_DIM * M_DIM) / BM, 1), 256, SMEM_DYN>>>(
            x, wsum, out,
            H_DIM, H_DIM, H_DIM,
            0, 0, 0);
}

// round 4
// speedup vs baseline: 1.0749x; 1.0749x over previous
#include <cuda_runtime.h>
#include <cstdint>
#include <cstddef>

// ---------------- problem dims ----------------
#define A_DIM 4
#define M_DIM 1024
#define H_DIM 1024
#define E_DIM 8
#define N_DIM 4096

// ---------------- tile config ----------------
#define BM 128
#define BN 128
#define BK 32
#define NSTAGE 3
// padded smem strides (floats) for conflict-free fragment LDS
#define LDA_S 36     /* A tile row stride: bank=(4g+q)%32 distinct     */
#define LDB_S 136    /* B tile row stride: bank=(8q+g)%32 distinct     */
#define A_STG_FLOATS (BM * LDA_S)          /* 4608  */
#define B_STG_FLOATS (BK * LDB_S)          /* 4352  */
#define STG_FLOATS   (A_STG_FLOATS + B_STG_FLOATS)   /* 8960 = 35840 B */
#define SMEM_DYN     (NSTAGE * STG_FLOATS * 4)       /* 107520 B -> 2 CTA/SM */

// ---------------- device scratch ----------------
__device__ float g_xr  [(size_t)A_DIM * M_DIM * H_DIM];   // 16 MB  rounded x
__device__ float g_w1r [(size_t)E_DIM * H_DIM * N_DIM];   // 128 MB rounded w1
__device__ float g_w2r [(size_t)E_DIM * N_DIM * H_DIM];   // 128 MB rounded w2
__device__ float g_part[(size_t)E_DIM * H_DIM * H_DIM];   // 32 MB per-expert partial W
__device__ float g_wsum[(size_t)H_DIM * H_DIM];           // 4 MB  combined W (rounded)

// ---------------- helpers ----------------
__device__ __forceinline__ uint32_t smem_u32(const void* p) {
    uint32_t a;
    asm("{ .reg .u64 t; cvta.to.shared.u64 t, %1; cvt.u32.u64 %0, t; }" : "=r"(a) : "l"(p));
    return a;
}
__device__ __forceinline__ float rna_tf32(float f) {   // round-to-nearest tf32, as float
    asm("cvt.rna.tf32.f32 %0, %0;" : "+f"(f));
    return f;
}
__device__ __forceinline__ void cp16(uint32_t dst, const float* src) {
    asm volatile("cp.async.cg.shared.global [%0], [%1], 16;\n"
                 :: "r"(dst), "l"(__cvta_generic_to_global(src)) : "memory");
}
__device__ __forceinline__ void cp_commit() {
    asm volatile("cp.async.commit_group;\n" ::: "memory");
}
__device__ __forceinline__ void mma_tf32(float* c, const uint32_t* a, const uint32_t* b) {
    asm volatile(
        "mma.sync.aligned.m16n8k8.row.col.f32.tf32.tf32.f32 "
        "{%0,%1,%2,%3}, {%4,%5,%6,%7}, {%8,%9}, {%0,%1,%2,%3};"
        : "+f"(c[0]), "+f"(c[1]), "+f"(c[2]), "+f"(c[3])
        : "r"(a[0]), "r"(a[1]), "r"(a[2]), "r"(a[3]), "r"(b[0]), "r"(b[1]));
}

// ---- streaming tf32 rounding: dst = rna_tf32(src), float4 granularity ----
__global__ void round_stream_ker(const float* __restrict__ src, float* __restrict__ dst) {
    size_t i = (size_t)blockIdx.x * blockDim.x + threadIdx.x;
    float4 v = reinterpret_cast<const float4*>(src)[i];
    v.x = rna_tf32(v.x); v.y = rna_tf32(v.y); v.z = rna_tf32(v.z); v.w = rna_tf32(v.w);
    reinterpret_cast<float4*>(dst)[i] = v;
}

// =============================================================================
// tf32 GEMM: C[BM x BN] = A[M x K](row-major, lda) * B[K x N](row-major, ldb)
// Operands MUST already be tf32-rounded. C written fp32.
// =============================================================================
template <int KB>   // number of BK-blocks in K
__global__ void __launch_bounds__(256, 2)
gemm_tf32_ker(const float* __restrict__ Ag, const float* __restrict__ Bg,
              float* __restrict__ Cg,
              int lda, int ldb, int ldc,
              size_t a_batch_stride, size_t b_batch_stride, size_t c_batch_stride) {
    extern __shared__ float sm[];

    const int tid  = threadIdx.x;
    const int lane = tid & 31;
    const int warp = tid >> 5;
    const int g = lane >> 2;          // group id 0..7
    const int q = lane & 3;           // thread-in-group 0..3
    const int wm = warp & 3;          // warp m index (4)
    const int wn = warp >> 2;         // warp n index (2)

    const int bz = blockIdx.z;
    const float* A = Ag + (size_t)bz * a_batch_stride + (size_t)blockIdx.y * BM * lda;
    const float* B = Bg + (size_t)bz * b_batch_stride + (size_t)blockIdx.x * BN;
    float*       C = Cg + (size_t)bz * c_batch_stride
                        + (size_t)blockIdx.y * BM * ldc + (size_t)blockIdx.x * BN;

    const uint32_t smem0 = smem_u32(sm);

    // ---- gmem -> smem load geometry (16B chunks) ----
    const int ar  = tid >> 3;          // A: base row (0..31), +32*i
    const int ac  = (tid & 7) * 4;     // A: float col
    const int br  = tid >> 5;          // B: base row (0..7), +8*i
    const int bc  = (tid & 31) * 4;    // B: float col

    auto load_stage = [&](int slot, int kb) {
        uint32_t sa = smem0 + (uint32_t)slot * (STG_FLOATS * 4);
        uint32_t sb = sa + A_STG_FLOATS * 4;
        const float* Ak = A + (size_t)kb * BK;
        const float* Bk = B + (size_t)kb * BK * ldb;
        #pragma unroll
        for (int i = 0; i < 4; i++) {
            int r = ar + 32 * i;
            cp16(sa + (uint32_t)(r * LDA_S + ac) * 4u, Ak + (size_t)r * lda + ac);
        }
        #pragma unroll
        for (int i = 0; i < 4; i++) {
            int r = br + 8 * i;
            cp16(sb + (uint32_t)(r * LDB_S + bc) * 4u, Bk + (size_t)r * ldb + bc);
        }
        cp_commit();
    };

    // ---- accumulators ----
    float c[2][8][4];
    #pragma unroll
    for (int mt = 0; mt < 2; mt++)
        #pragma unroll
        for (int nt = 0; nt < 8; nt++)
            #pragma unroll
            for (int i = 0; i < 4; i++) c[mt][nt][i] = 0.0f;

    // ---- prologue (NSTAGE-1 stages in flight) ----
    #pragma unroll
    for (int s = 0; s < NSTAGE - 1; s++) load_stage(s, s);

    int slot_c = 0;                // consume slot
    int slot_p = NSTAGE - 1;       // prefetch slot

    // ---- main loop ----
    #pragma unroll 1
    for (int kb = 0; kb < KB; ++kb) {
        asm volatile("cp.async.wait_group %0;\n" :: "n"(NSTAGE - 2) : "memory");
        __syncthreads();

        int pf = kb + NSTAGE - 1;
        if (pf < KB) load_stage(slot_p, pf);
        else         cp_commit();   // keep group count aligned
        if (++slot_p == NSTAGE) slot_p = 0;

        const uint32_t* As = reinterpret_cast<const uint32_t*>(sm + slot_c * STG_FLOATS);
        const uint32_t* Bs = As + A_STG_FLOATS;
        if (++slot_c == NSTAGE) slot_c = 0;

        #pragma unroll
        for (int ks = 0; ks < 4; ks++) {
            // A fragments: 2 m-tiles (data pre-rounded; raw 32b loads)
            uint32_t afr[2][4];
            #pragma unroll
            for (int mt = 0; mt < 2; mt++) {
                int r0 = wm * 32 + mt * 16 + g;
                int c0 = ks * 8 + q;
                afr[mt][0] = As[r0 * LDA_S + c0];
                afr[mt][1] = As[(r0 + 8) * LDA_S + c0];
                afr[mt][2] = As[r0 * LDA_S + c0 + 4];
                afr[mt][3] = As[(r0 + 8) * LDA_S + c0 + 4];
            }
            // B fragments: 8 n-tiles
            uint32_t bfr[8][2];
            #pragma unroll
            for (int nt = 0; nt < 8; nt++) {
                int col = wn * 64 + nt * 8 + g;
                int r0 = ks * 8 + q;
                bfr[nt][0] = Bs[r0 * LDB_S + col];
                bfr[nt][1] = Bs[(r0 + 4) * LDB_S + col];
            }
            #pragma unroll
            for (int mt = 0; mt < 2; mt++)
                #pragma unroll
                for (int nt = 0; nt < 8; nt++)
                    mma_tf32(c[mt][nt], afr[mt], bfr[nt]);
        }
    }

    // ---- epilogue: fp32 stores ----
    #pragma unroll
    for (int mt = 0; mt < 2; mt++) {
        #pragma unroll
        for (int nt = 0; nt < 8; nt++) {
            int r0  = wm * 32 + mt * 16 + g;
            int col = wn * 64 + nt * 8 + 2 * q;
            float2 v0 = make_float2(c[mt][nt][0], c[mt][nt][1]);
            float2 v1 = make_float2(c[mt][nt][2], c[mt][nt][3]);
            *reinterpret_cast<float2*>(C + (size_t)r0 * ldc + col)       = v0;
            *reinterpret_cast<float2*>(C + (size_t)(r0 + 8) * ldc + col) = v1;
        }
    }
}

// ---- reduce 8 expert partials into g_wsum, rounding the sum to tf32 ----
__global__ void reduce_experts_ker() {
    size_t i = (size_t)blockIdx.x * blockDim.x + threadIdx.x;  // float4 index
    const float4* p = reinterpret_cast<const float4*>(g_part);
    float4 acc = p[i];
    #pragma unroll
    for (int e = 1; e < E_DIM; e++) {
        float4 v = p[(size_t)e * (H_DIM * H_DIM / 4) + i];
        acc.x += v.x; acc.y += v.y; acc.z += v.z; acc.w += v.w;
    }
    acc.x = rna_tf32(acc.x); acc.y = rna_tf32(acc.y);
    acc.z = rna_tf32(acc.z); acc.w = rna_tf32(acc.w);
    reinterpret_cast<float4*>(g_wsum)[i] = acc;
}

// ================= launch =================
extern "C" void kernel_launch(void* const* d_in, const int* in_sizes, int n_in,
                              void* d_out, int out_size) {
    const float* x  = (const float*)d_in[0];
    const float* w1 = (const float*)d_in[1];   // [E][H][N]
    const float* w2 = (const float*)d_in[2];   // [E][N][H]
    float* out = (float*)d_out;                // [A][M][H]

    float* xr   = nullptr; cudaGetSymbolAddress((void**)&xr,   g_xr);
    float* w1r  = nullptr; cudaGetSymbolAddress((void**)&w1r,  g_w1r);
    float* w2r  = nullptr; cudaGetSymbolAddress((void**)&w2r,  g_w2r);
    float* part = nullptr; cudaGetSymbolAddress((void**)&part, g_part);
    float* wsum = nullptr; cudaGetSymbolAddress((void**)&wsum, g_wsum);

    cudaFuncSetAttribute(gemm_tf32_ker<N_DIM / BK>,
                         cudaFuncAttributeMaxDynamicSharedMemorySize, SMEM_DYN);
    cudaFuncSetAttribute(gemm_tf32_ker<H_DIM / BK>,
                         cudaFuncAttributeMaxDynamicSharedMemorySize, SMEM_DYN);

    // 0) pre-round everything to tf32 (removes all cvts from GEMM inner loops)
    round_stream_ker<<<(A_DIM * M_DIM * H_DIM / 4) / 256, 256>>>(x,  xr);   // 16 MB
    round_stream_ker<<<((size_t)E_DIM * H_DIM * N_DIM / 4) / 256, 256>>>(w1, w1r);
    round_stream_ker<<<((size_t)E_DIM * N_DIM * H_DIM / 4) / 256, 256>>>(w2, w2r);

    // 1) per-expert combine: g_part[e] = w1r[e] @ w2r[e]
    gemm_tf32_ker<N_DIM / BK>
        <<<dim3(H_DIM / BN, H_DIM / BM, E_DIM), 256, SMEM_DYN>>>(
            w1r, w2r, part,
            N_DIM, H_DIM, H_DIM,
            (size_t)H_DIM * N_DIM, (size_t)N_DIM * H_DIM, (size_t)H_DIM * H_DIM);

    // 2) reduce experts (+ tf32 rounding): g_wsum = rna(sum_e g_part[e])
    reduce_experts_ker<<<(H_DIM * H_DIM / 4) / 256, 256>>>();

    // 3) apply: out = xr @ W   (x as [A*M x H], single batch)
    gemm_tf32_ker<H_DIM / BK>
        <<<dim3(H_DIM / BN, (A_DIM * M_DIM) / BM, 1), 256, SMEM_DYN>>>(
            xr, wsum, out,
            H_DIM, H_DIM, H_DIM,
            0, 0, 0);
}

// round 5
// speedup vs baseline: 1.1088x; 1.0315x over previous
#include <cuda_runtime.h>
#include <cstdint>
#include <cstddef>

// ---------------- problem dims ----------------
#define A_DIM 4
#define M_DIM 1024
#define H_DIM 1024
#define E_DIM 8
#define N_DIM 4096

// ---------------- tile config ----------------
#define BM 128
#define BN 128
#define BK 32
#define NSTAGE 3
#define NTHREADS 128   /* 4 warps, warp tile 64x64 */
// padded smem strides (floats) for conflict-free fragment LDS
#define LDA_S 36     /* A tile row stride: bank=(4g+q)%32 distinct */
#define LDB_S 136    /* B tile row stride: bank=(8q+g)%32 distinct */
#define A_STG_FLOATS (BM * LDA_S)          /* 4608 */
#define B_STG_FLOATS (BK * LDB_S)          /* 4352 */
#define STG_FLOATS   (A_STG_FLOATS + B_STG_FLOATS)   /* 8960 = 35840 B */
#define SMEM_DYN     (NSTAGE * STG_FLOATS * 4)       /* 107520 B -> 2 CTA/SM */

// ---------------- device scratch ----------------
__device__ float g_xr  [(size_t)A_DIM * M_DIM * H_DIM];   // 16 MB  rounded x
__device__ float g_w1r [(size_t)E_DIM * H_DIM * N_DIM];   // 128 MB rounded w1
__device__ float g_w2r [(size_t)E_DIM * N_DIM * H_DIM];   // 128 MB rounded w2
__device__ float g_part[(size_t)E_DIM * H_DIM * H_DIM];   // 32 MB per-expert partial W
__device__ float g_wsum[(size_t)H_DIM * H_DIM];           // 4 MB  combined W (rounded)

// ---------------- helpers ----------------
__device__ __forceinline__ uint32_t smem_u32(const void* p) {
    uint32_t a;
    asm("{ .reg .u64 t; cvta.to.shared.u64 t, %1; cvt.u32.u64 %0, t; }" : "=r"(a) : "l"(p));
    return a;
}
__device__ __forceinline__ float rna_tf32(float f) {
    asm("cvt.rna.tf32.f32 %0, %0;" : "+f"(f));
    return f;
}
__device__ __forceinline__ void cp16(uint32_t dst, const float* src) {
    asm volatile("cp.async.cg.shared.global [%0], [%1], 16;\n"
                 :: "r"(dst), "l"(__cvta_generic_to_global(src)) : "memory");
}
__device__ __forceinline__ void cp_commit() {
    asm volatile("cp.async.commit_group;\n" ::: "memory");
}
__device__ __forceinline__ void mma_tf32(float* c, const uint32_t* a, const uint32_t* b) {
    asm volatile(
        "mma.sync.aligned.m16n8k8.row.col.f32.tf32.tf32.f32 "
        "{%0,%1,%2,%3}, {%4,%5,%6,%7}, {%8,%9}, {%0,%1,%2,%3};"
        : "+f"(c[0]), "+f"(c[1]), "+f"(c[2]), "+f"(c[3])
        : "r"(a[0]), "r"(a[1]), "r"(a[2]), "r"(a[3]), "r"(b[0]), "r"(b[1]));
}

// ---- streaming tf32 rounding ----
__global__ void round_stream_ker(const float* __restrict__ src, float* __restrict__ dst) {
    size_t i = (size_t)blockIdx.x * blockDim.x + threadIdx.x;
    float4 v = reinterpret_cast<const float4*>(src)[i];
    v.x = rna_tf32(v.x); v.y = rna_tf32(v.y); v.z = rna_tf32(v.z); v.w = rna_tf32(v.w);
    reinterpret_cast<float4*>(dst)[i] = v;
}

// =============================================================================
// tf32 GEMM: C[BM x BN] = A[M x K](row-major, lda) * B[K x N](row-major, ldb)
// 4 warps, 64x64 warp tile, double-buffered fragments. Operands pre-rounded.
// =============================================================================
template <int KB>
__global__ void __launch_bounds__(NTHREADS, 2)
gemm_tf32_ker(const float* __restrict__ Ag, const float* __restrict__ Bg,
              float* __restrict__ Cg,
              int lda, int ldb, int ldc,
              size_t a_batch_stride, size_t b_batch_stride, size_t c_batch_stride) {
    extern __shared__ float sm[];

    const int tid  = threadIdx.x;
    const int lane = tid & 31;
    const int warp = tid >> 5;
    const int g = lane >> 2;          // 0..7
    const int q = lane & 3;           // 0..3
    const int wm = warp & 1;          // warp m index (2)
    const int wn = warp >> 1;         // warp n index (2)

    const int bz = blockIdx.z;
    const float* A = Ag + (size_t)bz * a_batch_stride + (size_t)blockIdx.y * BM * lda;
    const float* B = Bg + (size_t)bz * b_batch_stride + (size_t)blockIdx.x * BN;
    float*       C = Cg + (size_t)bz * c_batch_stride
                        + (size_t)blockIdx.y * BM * ldc + (size_t)blockIdx.x * BN;

    const uint32_t smem0 = smem_u32(sm);

    // ---- gmem -> smem geometry (16B chunks, 128 threads: 8 A-chunks + 8 B-chunks each) ----
    const int ar = tid >> 3;            // A base row (0..15), +16*i
    const int ac = (tid & 7) * 4;       // A float col
    const int br = tid >> 5;            // B base row (0..3), +4*i
    const int bc = (tid & 31) * 4;      // B float col

    auto load_stage = [&](int slot, int kb) {
        uint32_t sa = smem0 + (uint32_t)slot * (STG_FLOATS * 4);
        uint32_t sb = sa + A_STG_FLOATS * 4;
        const float* Ak = A + (size_t)kb * BK;
        const float* Bk = B + (size_t)kb * BK * ldb;
        #pragma unroll
        for (int i = 0; i < 8; i++) {
            int r = ar + 16 * i;
            cp16(sa + (uint32_t)(r * LDA_S + ac) * 4u, Ak + (size_t)r * lda + ac);
        }
        #pragma unroll
        for (int i = 0; i < 8; i++) {
            int r = br + 4 * i;
            cp16(sb + (uint32_t)(r * LDB_S + bc) * 4u, Bk + (size_t)r * ldb + bc);
        }
        cp_commit();
    };

    // ---- accumulators: 4 m-tiles x 8 n-tiles x 4 ----
    float c[4][8][4];
    #pragma unroll
    for (int mt = 0; mt < 4; mt++)
        #pragma unroll
        for (int nt = 0; nt < 8; nt++)
            #pragma unroll
            for (int i = 0; i < 4; i++) c[mt][nt][i] = 0.0f;

    #pragma unroll
    for (int s = 0; s < NSTAGE - 1; s++) load_stage(s, s);

    int slot_c = 0, slot_p = NSTAGE - 1;

    // fragment double buffers
    uint32_t afr[2][4][4];
    uint32_t bfr[2][8][2];

    auto load_frags = [&](const uint32_t* As, const uint32_t* Bs, int ks, int buf) {
        #pragma unroll
        for (int mt = 0; mt < 4; mt++) {
            int r0 = wm * 64 + mt * 16 + g;
            int c0 = ks * 8 + q;
            afr[buf][mt][0] = As[r0 * LDA_S + c0];
            afr[buf][mt][1] = As[(r0 + 8) * LDA_S + c0];
            afr[buf][mt][2] = As[r0 * LDA_S + c0 + 4];
            afr[buf][mt][3] = As[(r0 + 8) * LDA_S + c0 + 4];
        }
        #pragma unroll
        for (int nt = 0; nt < 8; nt++) {
            int col = wn * 64 + nt * 8 + g;
            int r0 = ks * 8 + q;
            bfr[buf][nt][0] = Bs[r0 * LDB_S + col];
            bfr[buf][nt][1] = Bs[(r0 + 4) * LDB_S + col];
        }
    };

    #pragma unroll 1
    for (int kb = 0; kb < KB; ++kb) {
        asm volatile("cp.async.wait_group %0;\n" :: "n"(NSTAGE - 2) : "memory");
        __syncthreads();

        int pf = kb + NSTAGE - 1;
        if (pf < KB) load_stage(slot_p, pf);
        else         cp_commit();
        if (++slot_p == NSTAGE) slot_p = 0;

        const uint32_t* As = reinterpret_cast<const uint32_t*>(sm + slot_c * STG_FLOATS);
        const uint32_t* Bs = As + A_STG_FLOATS;
        if (++slot_c == NSTAGE) slot_c = 0;

        load_frags(As, Bs, 0, 0);
        #pragma unroll
        for (int ks = 0; ks < 4; ks++) {
            int cur = ks & 1;
            if (ks < 3) load_frags(As, Bs, ks + 1, cur ^ 1);
            #pragma unroll
            for (int mt = 0; mt < 4; mt++)
                #pragma unroll
                for (int nt = 0; nt < 8; nt++)
                    mma_tf32(c[mt][nt], afr[cur][mt], bfr[cur][nt]);
        }
    }

    // ---- epilogue ----
    #pragma unroll
    for (int mt = 0; mt < 4; mt++) {
        #pragma unroll
        for (int nt = 0; nt < 8; nt++) {
            int r0  = wm * 64 + mt * 16 + g;
            int col = wn * 64 + nt * 8 + 2 * q;
            float2 v0 = make_float2(c[mt][nt][0], c[mt][nt][1]);
            float2 v1 = make_float2(c[mt][nt][2], c[mt][nt][3]);
            *reinterpret_cast<float2*>(C + (size_t)r0 * ldc + col)       = v0;
            *reinterpret_cast<float2*>(C + (size_t)(r0 + 8) * ldc + col) = v1;
        }
    }
}

// ---- reduce 8 expert partials into g_wsum, rounding the sum to tf32 ----
__global__ void reduce_experts_ker() {
    size_t i = (size_t)blockIdx.x * blockDim.x + threadIdx.x;
    const float4* p = reinterpret_cast<const float4*>(g_part);
    float4 acc = p[i];
    #pragma unroll
    for (int e = 1; e < E_DIM; e++) {
        float4 v = p[(size_t)e * (H_DIM * H_DIM / 4) + i];
        acc.x += v.x; acc.y += v.y; acc.z += v.z; acc.w += v.w;
    }
    acc.x = rna_tf32(acc.x); acc.y = rna_tf32(acc.y);
    acc.z = rna_tf32(acc.z); acc.w = rna_tf32(acc.w);
    reinterpret_cast<float4*>(g_wsum)[i] = acc;
}

// ================= launch =================
extern "C" void kernel_launch(void* const* d_in, const int* in_sizes, int n_in,
                              void* d_out, int out_size) {
    const float* x  = (const float*)d_in[0];
    const float* w1 = (const float*)d_in[1];   // [E][H][N]
    const float* w2 = (const float*)d_in[2];   // [E][N][H]
    float* out = (float*)d_out;                // [A][M][H]

    float* xr   = nullptr; cudaGetSymbolAddress((void**)&xr,   g_xr);
    float* w1r  = nullptr; cudaGetSymbolAddress((void**)&w1r,  g_w1r);
    float* w2r  = nullptr; cudaGetSymbolAddress((void**)&w2r,  g_w2r);
    float* part = nullptr; cudaGetSymbolAddress((void**)&part, g_part);
    float* wsum = nullptr; cudaGetSymbolAddress((void**)&wsum, g_wsum);

    cudaFuncSetAttribute(gemm_tf32_ker<N_DIM / BK>,
                         cudaFuncAttributeMaxDynamicSharedMemorySize, SMEM_DYN);
    cudaFuncSetAttribute(gemm_tf32_ker<H_DIM / BK>,
                         cudaFuncAttributeMaxDynamicSharedMemorySize, SMEM_DYN);

    // 0) pre-round to tf32
    round_stream_ker<<<(A_DIM * M_DIM * H_DIM / 4) / 256, 256>>>(x,  xr);
    round_stream_ker<<<((size_t)E_DIM * H_DIM * N_DIM / 4) / 256, 256>>>(w1, w1r);
    round_stream_ker<<<((size_t)E_DIM * N_DIM * H_DIM / 4) / 256, 256>>>(w2, w2r);

    // 1) per-expert combine: g_part[e] = w1r[e] @ w2r[e]
    gemm_tf32_ker<N_DIM / BK>
        <<<dim3(H_DIM / BN, H_DIM / BM, E_DIM), NTHREADS, SMEM_DYN>>>(
            w1r, w2r, part,
            N_DIM, H_DIM, H_DIM,
            (size_t)H_DIM * N_DIM, (size_t)N_DIM * H_DIM, (size_t)H_DIM * H_DIM);

    // 2) reduce experts (+ tf32 rounding)
    reduce_experts_ker<<<(H_DIM * H_DIM / 4) / 256, 256>>>();

    // 3) apply: out = xr @ W
    gemm_tf32_ker<H_DIM / BK>
        <<<dim3(H_DIM / BN, (A_DIM * M_DIM) / BM, 1), NTHREADS, SMEM_DYN>>>(
            xr, wsum, out,
            H_DIM, H_DIM, H_DIM,
            0, 0, 0);
}

// round 6
// speedup vs baseline: 1.1762x; 1.0607x over previous
#include <cuda_runtime.h>
#include <cstdint>
#include <cstddef>

// ---------------- problem dims ----------------
#define A_DIM 4
#define M_DIM 1024
#define H_DIM 1024
#define E_DIM 8
#define N_DIM 4096

// ---------------- tile config ----------------
#define BM 128
#define BN 128
#define BK 32
#define NSTAGE 3
#define NTHREADS 128   /* 4 warps, warp tile 64x64 */
// padded smem strides (floats) for conflict-free fragment LDS
#define LDA_S 36     /* A tile row stride: bank=(4g+q)%32 distinct */
#define LDB_S 136    /* B tile row stride: bank=(8q+g)%32 distinct */
#define A_STG_FLOATS (BM * LDA_S)          /* 4608 */
#define B_STG_FLOATS (BK * LDB_S)          /* 4352 */
#define STG_FLOATS   (A_STG_FLOATS + B_STG_FLOATS)   /* 8960 = 35840 B */
#define SMEM_DYN     (NSTAGE * STG_FLOATS * 4)       /* 107520 B -> 2 CTA/SM */

// ---------------- device scratch ----------------
__device__ float g_part[(size_t)E_DIM * H_DIM * H_DIM];   // 32 MB per-expert partial W
__device__ float g_wsum[(size_t)H_DIM * H_DIM];           // 4 MB  combined W (tf32-rounded)

// ---------------- helpers ----------------
__device__ __forceinline__ uint32_t smem_u32(const void* p) {
    uint32_t a;
    asm("{ .reg .u64 t; cvta.to.shared.u64 t, %1; cvt.u32.u64 %0, t; }" : "=r"(a) : "l"(p));
    return a;
}
__device__ __forceinline__ float rna_tf32(float f) {
    asm("cvt.rna.tf32.f32 %0, %0;" : "+f"(f));
    return f;
}
__device__ __forceinline__ uint32_t rna_tf32_u(uint32_t u) {
    asm("cvt.rna.tf32.f32 %0, %0;" : "+r"(u));
    return u;
}
__device__ __forceinline__ void cp16(uint32_t dst, const float* src) {
    asm volatile("cp.async.cg.shared.global [%0], [%1], 16;\n"
                 :: "r"(dst), "l"(__cvta_generic_to_global(src)) : "memory");
}
__device__ __forceinline__ void cp_commit() {
    asm volatile("cp.async.commit_group;\n" ::: "memory");
}
__device__ __forceinline__ void mma_tf32(float* c, const uint32_t* a, const uint32_t* b) {
    asm volatile(
        "mma.sync.aligned.m16n8k8.row.col.f32.tf32.tf32.f32 "
        "{%0,%1,%2,%3}, {%4,%5,%6,%7}, {%8,%9}, {%0,%1,%2,%3};"
        : "+f"(c[0]), "+f"(c[1]), "+f"(c[2]), "+f"(c[3])
        : "r"(a[0]), "r"(a[1]), "r"(a[2]), "r"(a[3]), "r"(b[0]), "r"(b[1]));
}

// =============================================================================
// tf32 GEMM: C[BM x BN] = A[M x K](row-major, lda) * B[K x N](row-major, ldb)
// 4 warps, 64x64 warp tile, double-buffered fragments.
// RND_A / RND_B: round that operand to tf32 (rna) at fragment-load time.
// =============================================================================
template <int KB, bool RND_A, bool RND_B>
__global__ void __launch_bounds__(NTHREADS, 2)
gemm_tf32_ker(const float* __restrict__ Ag, const float* __restrict__ Bg,
              float* __restrict__ Cg,
              int lda, int ldb, int ldc,
              size_t a_batch_stride, size_t b_batch_stride, size_t c_batch_stride) {
    extern __shared__ float sm[];

    const int tid  = threadIdx.x;
    const int lane = tid & 31;
    const int warp = tid >> 5;
    const int g = lane >> 2;          // 0..7
    const int q = lane & 3;           // 0..3
    const int wm = warp & 1;          // warp m index (2)
    const int wn = warp >> 1;         // warp n index (2)

    const int bz = blockIdx.z;
    const float* A = Ag + (size_t)bz * a_batch_stride + (size_t)blockIdx.y * BM * lda;
    const float* B = Bg + (size_t)bz * b_batch_stride + (size_t)blockIdx.x * BN;
    float*       C = Cg + (size_t)bz * c_batch_stride
                        + (size_t)blockIdx.y * BM * ldc + (size_t)blockIdx.x * BN;

    const uint32_t smem0 = smem_u32(sm);

    // ---- gmem -> smem geometry (16B chunks, 128 threads: 8 A + 8 B chunks each) ----
    const int ar = tid >> 3;            // A base row (0..15), +16*i
    const int ac = (tid & 7) * 4;       // A float col
    const int br = tid >> 5;            // B base row (0..3), +4*i
    const int bc = (tid & 31) * 4;      // B float col

    auto load_stage = [&](int slot, int kb) {
        uint32_t sa = smem0 + (uint32_t)slot * (STG_FLOATS * 4);
        uint32_t sb = sa + A_STG_FLOATS * 4;
        const float* Ak = A + (size_t)kb * BK;
        const float* Bk = B + (size_t)kb * BK * ldb;
        #pragma unroll
        for (int i = 0; i < 8; i++) {
            int r = ar + 16 * i;
            cp16(sa + (uint32_t)(r * LDA_S + ac) * 4u, Ak + (size_t)r * lda + ac);
        }
        #pragma unroll
        for (int i = 0; i < 8; i++) {
            int r = br + 4 * i;
            cp16(sb + (uint32_t)(r * LDB_S + bc) * 4u, Bk + (size_t)r * ldb + bc);
        }
        cp_commit();
    };

    // ---- accumulators: 4 m-tiles x 8 n-tiles x 4 ----
    float c[4][8][4];
    #pragma unroll
    for (int mt = 0; mt < 4; mt++)
        #pragma unroll
        for (int nt = 0; nt < 8; nt++)
            #pragma unroll
            for (int i = 0; i < 4; i++) c[mt][nt][i] = 0.0f;

    #pragma unroll
    for (int s = 0; s < NSTAGE - 1; s++) load_stage(s, s);

    int slot_c = 0, slot_p = NSTAGE - 1;

    // fragment double buffers
    uint32_t afr[2][4][4];
    uint32_t bfr[2][8][2];

    auto load_frags = [&](const uint32_t* As, const uint32_t* Bs, int ks, int buf) {
        #pragma unroll
        for (int mt = 0; mt < 4; mt++) {
            int r0 = wm * 64 + mt * 16 + g;
            int c0 = ks * 8 + q;
            uint32_t v0 = As[r0 * LDA_S + c0];
            uint32_t v1 = As[(r0 + 8) * LDA_S + c0];
            uint32_t v2 = As[r0 * LDA_S + c0 + 4];
            uint32_t v3 = As[(r0 + 8) * LDA_S + c0 + 4];
            if (RND_A) { v0 = rna_tf32_u(v0); v1 = rna_tf32_u(v1);
                         v2 = rna_tf32_u(v2); v3 = rna_tf32_u(v3); }
            afr[buf][mt][0] = v0; afr[buf][mt][1] = v1;
            afr[buf][mt][2] = v2; afr[buf][mt][3] = v3;
        }
        #pragma unroll
        for (int nt = 0; nt < 8; nt++) {
            int col = wn * 64 + nt * 8 + g;
            int r0 = ks * 8 + q;
            uint32_t v0 = Bs[r0 * LDB_S + col];
            uint32_t v1 = Bs[(r0 + 4) * LDB_S + col];
            if (RND_B) { v0 = rna_tf32_u(v0); v1 = rna_tf32_u(v1); }
            bfr[buf][nt][0] = v0; bfr[buf][nt][1] = v1;
        }
    };

    #pragma unroll 1
    for (int kb = 0; kb < KB; ++kb) {
        asm volatile("cp.async.wait_group %0;\n" :: "n"(NSTAGE - 2) : "memory");
        __syncthreads();

        int pf = kb + NSTAGE - 1;
        if (pf < KB) load_stage(slot_p, pf);
        else         cp_commit();
        if (++slot_p == NSTAGE) slot_p = 0;

        const uint32_t* As = reinterpret_cast<const uint32_t*>(sm + slot_c * STG_FLOATS);
        const uint32_t* Bs = As + A_STG_FLOATS;
        if (++slot_c == NSTAGE) slot_c = 0;

        load_frags(As, Bs, 0, 0);
        #pragma unroll
        for (int ks = 0; ks < 4; ks++) {
            int cur = ks & 1;
            if (ks < 3) load_frags(As, Bs, ks + 1, cur ^ 1);
            #pragma unroll
            for (int mt = 0; mt < 4; mt++)
                #pragma unroll
                for (int nt = 0; nt < 8; nt++)
                    mma_tf32(c[mt][nt], afr[cur][mt], bfr[cur][nt]);
        }
    }

    // ---- epilogue ----
    #pragma unroll
    for (int mt = 0; mt < 4; mt++) {
        #pragma unroll
        for (int nt = 0; nt < 8; nt++) {
            int r0  = wm * 64 + mt * 16 + g;
            int col = wn * 64 + nt * 8 + 2 * q;
            float2 v0 = make_float2(c[mt][nt][0], c[mt][nt][1]);
            float2 v1 = make_float2(c[mt][nt][2], c[mt][nt][3]);
            *reinterpret_cast<float2*>(C + (size_t)r0 * ldc + col)       = v0;
            *reinterpret_cast<float2*>(C + (size_t)(r0 + 8) * ldc + col) = v1;
        }
    }
}

// ---- reduce 8 expert partials into g_wsum, rounding the sum to tf32 ----
__global__ void reduce_experts_ker() {
    size_t i = (size_t)blockIdx.x * blockDim.x + threadIdx.x;
    const float4* p = reinterpret_cast<const float4*>(g_part);
    float4 acc = p[i];
    #pragma unroll
    for (int e = 1; e < E_DIM; e++) {
        float4 v = p[(size_t)e * (H_DIM * H_DIM / 4) + i];
        acc.x += v.x; acc.y += v.y; acc.z += v.z; acc.w += v.w;
    }
    acc.x = rna_tf32(acc.x); acc.y = rna_tf32(acc.y);
    acc.z = rna_tf32(acc.z); acc.w = rna_tf32(acc.w);
    reinterpret_cast<float4*>(g_wsum)[i] = acc;
}

// ================= launch =================
extern "C" void kernel_launch(void* const* d_in, const int* in_sizes, int n_in,
                              void* d_out, int out_size) {
    const float* x  = (const float*)d_in[0];
    const float* w1 = (const float*)d_in[1];   // [E][H][N]
    const float* w2 = (const float*)d_in[2];   // [E][N][H]
    float* out = (float*)d_out;                // [A][M][H]

    float* part = nullptr; cudaGetSymbolAddress((void**)&part, g_part);
    float* wsum = nullptr; cudaGetSymbolAddress((void**)&wsum, g_wsum);

    cudaFuncSetAttribute((const void*)gemm_tf32_ker<N_DIM / BK, true, true>,
                         cudaFuncAttributeMaxDynamicSharedMemorySize, SMEM_DYN);
    cudaFuncSetAttribute((const void*)gemm_tf32_ker<H_DIM / BK, true, false>,
                         cudaFuncAttributeMaxDynamicSharedMemorySize, SMEM_DYN);

    // 1) per-expert combine: g_part[e] = rna(w1[e]) @ rna(w2[e])  (rounding fused in frag loads)
    gemm_tf32_ker<N_DIM / BK, true, true>
        <<<dim3(H_DIM / BN, H_DIM / BM, E_DIM), NTHREADS, SMEM_DYN>>>(
            w1, w2, part,
            N_DIM, H_DIM, H_DIM,
            (size_t)H_DIM * N_DIM, (size_t)N_DIM * H_DIM, (size_t)H_DIM * H_DIM);

    // 2) reduce experts (+ tf32 rounding of the sum)
    reduce_experts_ker<<<(H_DIM * H_DIM / 4) / 256, 256>>>();

    // 3) apply: out = rna(x) @ W   (x rounded in frag loads; W pre-rounded)
    gemm_tf32_ker<H_DIM / BK, true, false>
        <<<dim3(H_DIM / BN, (A_DIM * M_DIM) / BM, 1), NTHREADS, SMEM_DYN>>>(
            x, wsum, out,
            H_DIM, H_DIM, H_DIM,
            0, 0, 0);
}

// round 7
// speedup vs baseline: 1.2571x; 1.0688x over previous
#include <cuda_runtime.h>
#include <cstdint>
#include <cstddef>

// ---------------- problem dims ----------------
#define A_DIM 4
#define M_DIM 1024
#define H_DIM 1024
#define E_DIM 8
#define N_DIM 4096
#define SPLITK_C 4     /* split-K factor for the combine GEMM */

// ---------------- tile config ----------------
#define BM 128
#define BN 128
#define BK 32
#define NSTAGE 3
#define NTHREADS 128   /* 4 warps, warp tile 64x64 */
// padded smem strides (floats) for conflict-free fragment LDS
#define LDA_S 36     /* A tile row stride: bank=(4g+q)%32 distinct */
#define LDB_S 136    /* B tile row stride: bank=(8q+g)%32 distinct */
#define A_STG_FLOATS (BM * LDA_S)          /* 4608 */
#define B_STG_FLOATS (BK * LDB_S)          /* 4352 */
#define STG_FLOATS   (A_STG_FLOATS + B_STG_FLOATS)   /* 8960 = 35840 B */
#define SMEM_DYN     (NSTAGE * STG_FLOATS * 4)       /* 107520 B -> 2 CTA/SM */

// ---------------- device scratch ----------------
__device__ float g_part[(size_t)E_DIM * SPLITK_C * H_DIM * H_DIM]; // 128 MB partials
__device__ float g_wsum[(size_t)H_DIM * H_DIM];                    // 4 MB combined W

// ---------------- helpers ----------------
__device__ __forceinline__ uint32_t smem_u32(const void* p) {
    uint32_t a;
    asm("{ .reg .u64 t; cvta.to.shared.u64 t, %1; cvt.u32.u64 %0, t; }" : "=r"(a) : "l"(p));
    return a;
}
__device__ __forceinline__ float rna_tf32(float f) {
    asm("cvt.rna.tf32.f32 %0, %0;" : "+f"(f));
    return f;
}
__device__ __forceinline__ uint32_t rna_tf32_u(uint32_t u) {
    asm("cvt.rna.tf32.f32 %0, %0;" : "+r"(u));
    return u;
}
__device__ __forceinline__ void cp16(uint32_t dst, const float* src) {
    asm volatile("cp.async.cg.shared.global [%0], [%1], 16;\n"
                 :: "r"(dst), "l"(__cvta_generic_to_global(src)) : "memory");
}
__device__ __forceinline__ void cp_commit() {
    asm volatile("cp.async.commit_group;\n" ::: "memory");
}
__device__ __forceinline__ void mma_tf32(float* c, const uint32_t* a, const uint32_t* b) {
    asm volatile(
        "mma.sync.aligned.m16n8k8.row.col.f32.tf32.tf32.f32 "
        "{%0,%1,%2,%3}, {%4,%5,%6,%7}, {%8,%9}, {%0,%1,%2,%3};"
        : "+f"(c[0]), "+f"(c[1]), "+f"(c[2]), "+f"(c[3])
        : "r"(a[0]), "r"(a[1]), "r"(a[2]), "r"(a[3]), "r"(b[0]), "r"(b[1]));
}

// =============================================================================
// tf32 GEMM with optional split-K batching.
// blockIdx.z: zo = z / SPLITK (logical batch), s = z % SPLITK (K-slice).
// C slice written to Cg + z * c_batch_stride (partials; reduced later).
// RND_A / RND_B: round operand to tf32 (rna) at fragment-load time.
// =============================================================================
template <int KB, int SPLITK, bool RND_A, bool RND_B>
__global__ void __launch_bounds__(NTHREADS, 2)
gemm_tf32_ker(const float* __restrict__ Ag, const float* __restrict__ Bg,
              float* __restrict__ Cg,
              int lda, int ldb, int ldc,
              size_t a_batch_stride, size_t b_batch_stride, size_t c_batch_stride) {
    extern __shared__ float sm[];

    const int tid  = threadIdx.x;
    const int lane = tid & 31;
    const int warp = tid >> 5;
    const int g = lane >> 2;          // 0..7
    const int q = lane & 3;           // 0..3
    const int wm = warp & 1;          // warp m index (2)
    const int wn = warp >> 1;         // warp n index (2)

    const int bz = blockIdx.z;
    const int zo = bz / SPLITK;
    const int ks_slice = bz % SPLITK;

    const float* A = Ag + (size_t)zo * a_batch_stride
                        + (size_t)ks_slice * KB * BK
                        + (size_t)blockIdx.y * BM * lda;
    const float* B = Bg + (size_t)zo * b_batch_stride
                        + (size_t)ks_slice * KB * BK * ldb
                        + (size_t)blockIdx.x * BN;
    float*       C = Cg + (size_t)bz * c_batch_stride
                        + (size_t)blockIdx.y * BM * ldc + (size_t)blockIdx.x * BN;

    const uint32_t smem0 = smem_u32(sm);

    // ---- gmem -> smem geometry (16B chunks, 128 threads: 8 A + 8 B chunks each) ----
    const int ar = tid >> 3;            // A base row (0..15), +16*i
    const int ac = (tid & 7) * 4;       // A float col
    const int br = tid >> 5;            // B base row (0..3), +4*i
    const int bc = (tid & 31) * 4;      // B float col

    auto load_stage = [&](int slot, int kb) {
        uint32_t sa = smem0 + (uint32_t)slot * (STG_FLOATS * 4);
        uint32_t sb = sa + A_STG_FLOATS * 4;
        const float* Ak = A + (size_t)kb * BK;
        const float* Bk = B + (size_t)kb * BK * ldb;
        #pragma unroll
        for (int i = 0; i < 8; i++) {
            int r = ar + 16 * i;
            cp16(sa + (uint32_t)(r * LDA_S + ac) * 4u, Ak + (size_t)r * lda + ac);
        }
        #pragma unroll
        for (int i = 0; i < 8; i++) {
            int r = br + 4 * i;
            cp16(sb + (uint32_t)(r * LDB_S + bc) * 4u, Bk + (size_t)r * ldb + bc);
        }
        cp_commit();
    };

    // ---- accumulators: 4 m-tiles x 8 n-tiles x 4 ----
    float c[4][8][4];
    #pragma unroll
    for (int mt = 0; mt < 4; mt++)
        #pragma unroll
        for (int nt = 0; nt < 8; nt++)
            #pragma unroll
            for (int i = 0; i < 4; i++) c[mt][nt][i] = 0.0f;

    #pragma unroll
    for (int s = 0; s < NSTAGE - 1; s++) load_stage(s, s);

    int slot_c = 0, slot_p = NSTAGE - 1;

    uint32_t afr[2][4][4];
    uint32_t bfr[2][8][2];

    auto load_frags = [&](const uint32_t* As, const uint32_t* Bs, int ks, int buf) {
        #pragma unroll
        for (int mt = 0; mt < 4; mt++) {
            int r0 = wm * 64 + mt * 16 + g;
            int c0 = ks * 8 + q;
            uint32_t v0 = As[r0 * LDA_S + c0];
            uint32_t v1 = As[(r0 + 8) * LDA_S + c0];
            uint32_t v2 = As[r0 * LDA_S + c0 + 4];
            uint32_t v3 = As[(r0 + 8) * LDA_S + c0 + 4];
            if (RND_A) { v0 = rna_tf32_u(v0); v1 = rna_tf32_u(v1);
                         v2 = rna_tf32_u(v2); v3 = rna_tf32_u(v3); }
            afr[buf][mt][0] = v0; afr[buf][mt][1] = v1;
            afr[buf][mt][2] = v2; afr[buf][mt][3] = v3;
        }
        #pragma unroll
        for (int nt = 0; nt < 8; nt++) {
            int col = wn * 64 + nt * 8 + g;
            int r0 = ks * 8 + q;
            uint32_t v0 = Bs[r0 * LDB_S + col];
            uint32_t v1 = Bs[(r0 + 4) * LDB_S + col];
            if (RND_B) { v0 = rna_tf32_u(v0); v1 = rna_tf32_u(v1); }
            bfr[buf][nt][0] = v0; bfr[buf][nt][1] = v1;
        }
    };

    #pragma unroll 1
    for (int kb = 0; kb < KB; ++kb) {
        asm volatile("cp.async.wait_group %0;\n" :: "n"(NSTAGE - 2) : "memory");
        __syncthreads();

        int pf = kb + NSTAGE - 1;
        if (pf < KB) load_stage(slot_p, pf);
        else         cp_commit();
        if (++slot_p == NSTAGE) slot_p = 0;

        const uint32_t* As = reinterpret_cast<const uint32_t*>(sm + slot_c * STG_FLOATS);
        const uint32_t* Bs = As + A_STG_FLOATS;
        if (++slot_c == NSTAGE) slot_c = 0;

        load_frags(As, Bs, 0, 0);
        #pragma unroll
        for (int ks = 0; ks < 4; ks++) {
            int cur = ks & 1;
            if (ks < 3) load_frags(As, Bs, ks + 1, cur ^ 1);
            #pragma unroll
            for (int mt = 0; mt < 4; mt++)
                #pragma unroll
                for (int nt = 0; nt < 8; nt++)
                    mma_tf32(c[mt][nt], afr[cur][mt], bfr[cur][nt]);
        }
    }

    // ---- epilogue ----
    #pragma unroll
    for (int mt = 0; mt < 4; mt++) {
        #pragma unroll
        for (int nt = 0; nt < 8; nt++) {
            int r0  = wm * 64 + mt * 16 + g;
            int col = wn * 64 + nt * 8 + 2 * q;
            float2 v0 = make_float2(c[mt][nt][0], c[mt][nt][1]);
            float2 v1 = make_float2(c[mt][nt][2], c[mt][nt][3]);
            *reinterpret_cast<float2*>(C + (size_t)r0 * ldc + col)       = v0;
            *reinterpret_cast<float2*>(C + (size_t)(r0 + 8) * ldc + col) = v1;
        }
    }
}

// ---- reduce E*SPLITK partials into g_wsum, rounding the sum to tf32 ----
__global__ void reduce_experts_ker() {
    size_t i = (size_t)blockIdx.x * blockDim.x + threadIdx.x;  // float4 index
    const float4* p = reinterpret_cast<const float4*>(g_part);
    float4 acc = p[i];
    #pragma unroll
    for (int e = 1; e < E_DIM * SPLITK_C; e++) {
        float4 v = p[(size_t)e * (H_DIM * H_DIM / 4) + i];
        acc.x += v.x; acc.y += v.y; acc.z += v.z; acc.w += v.w;
    }
    acc.x = rna_tf32(acc.x); acc.y = rna_tf32(acc.y);
    acc.z = rna_tf32(acc.z); acc.w = rna_tf32(acc.w);
    reinterpret_cast<float4*>(g_wsum)[i] = acc;
}

// ================= launch =================
extern "C" void kernel_launch(void* const* d_in, const int* in_sizes, int n_in,
                              void* d_out, int out_size) {
    const float* x  = (const float*)d_in[0];
    const float* w1 = (const float*)d_in[1];   // [E][H][N]
    const float* w2 = (const float*)d_in[2];   // [E][N][H]
    float* out = (float*)d_out;                // [A][M][H]

    float* part = nullptr; cudaGetSymbolAddress((void**)&part, g_part);
    float* wsum = nullptr; cudaGetSymbolAddress((void**)&wsum, g_wsum);

    constexpr int KB_C = (N_DIM / BK) / SPLITK_C;   // 32 kb-iters per combine CTA
    constexpr int KB_A = H_DIM / BK;                // 32 kb-iters for apply

    cudaFuncSetAttribute((const void*)gemm_tf32_ker<KB_C, SPLITK_C, true, true>,
                         cudaFuncAttributeMaxDynamicSharedMemorySize, SMEM_DYN);
    cudaFuncSetAttribute((const void*)gemm_tf32_ker<KB_A, 1, true, false>,
                         cudaFuncAttributeMaxDynamicSharedMemorySize, SMEM_DYN);

    // 1) per-expert, split-K combine: g_part[e][s] = rna(w1[e])_Ks @ rna(w2[e])_Ks
    //    grid.z = E*SPLITK = 32 -> 2048 CTAs (6.9 waves @ 2 CTA/SM, ~99% slot util)
    gemm_tf32_ker<KB_C, SPLITK_C, true, true>
        <<<dim3(H_DIM / BN, H_DIM / BM, E_DIM * SPLITK_C), NTHREADS, SMEM_DYN>>>(
            w1, w2, part,
            N_DIM, H_DIM, H_DIM,
            (size_t)H_DIM * N_DIM, (size_t)N_DIM * H_DIM, (size_t)H_DIM * H_DIM);

    // 2) reduce E*SPLITK partials (+ tf32 rounding of the sum)
    reduce_experts_ker<<<(H_DIM * H_DIM / 4) / 256, 256>>>();

    // 3) apply: out = rna(x) @ W   (W pre-rounded by reduce)
    gemm_tf32_ker<KB_A, 1, true, false>
        <<<dim3(H_DIM / BN, (A_DIM * M_DIM) / BM, 1), NTHREADS, SMEM_DYN>>>(
            x, wsum, out,
            H_DIM, H_DIM, H_DIM,
            0, 0, 0);
}

// round 8
// speedup vs baseline: 1.3117x; 1.0434x over previous
#include <cuda_runtime.h>
#include <cstdint>
#include <cstddef>

// ---------------- problem dims ----------------
#define A_DIM 4
#define M_DIM 1024
#define H_DIM 1024
#define E_DIM 8
#define N_DIM 4096
#define SPLITK_C 4     /* split-K factor for the combine GEMM */

// ---------------- tile config ----------------
#define BM 128
#define BN 128
#define BK 32
#define NSTAGE 3
#define NTHREADS 128   /* 4 warps, warp tile 64x64 */
// padded smem strides (floats) for conflict-free fragment LDS
#define LDA_S 36     /* A tile row stride: bank=(4g+q)%32 distinct */
#define LDB_S 136    /* B tile row stride: bank=(8q+g)%32 distinct */
#define A_STG_FLOATS (BM * LDA_S)          /* 4608 */
#define B_STG_FLOATS (BK * LDB_S)          /* 4352 */
#define STG_FLOATS   (A_STG_FLOATS + B_STG_FLOATS)   /* 8960 = 35840 B */
#define SMEM_DYN     (NSTAGE * STG_FLOATS * 4)       /* 107520 B -> 2 CTA/SM */

// ---------------- device scratch ----------------
__device__ float g_part[(size_t)E_DIM * SPLITK_C * H_DIM * H_DIM]; // 128 MB partials
__device__ float g_wsum[(size_t)H_DIM * H_DIM];                    // 4 MB combined W

// ---------------- helpers ----------------
__device__ __forceinline__ uint32_t smem_u32(const void* p) {
    uint32_t a;
    asm("{ .reg .u64 t; cvta.to.shared.u64 t, %1; cvt.u32.u64 %0, t; }" : "=r"(a) : "l"(p));
    return a;
}
__device__ __forceinline__ float rna_tf32(float f) {
    asm("cvt.rna.tf32.f32 %0, %0;" : "+f"(f));
    return f;
}
__device__ __forceinline__ uint32_t rna_tf32_u(uint32_t u) {
    asm("cvt.rna.tf32.f32 %0, %0;" : "+r"(u));
    return u;
}
__device__ __forceinline__ void cp16(uint32_t dst, const float* src) {
    asm volatile("cp.async.cg.shared.global [%0], [%1], 16;\n"
                 :: "r"(dst), "l"(__cvta_generic_to_global(src)) : "memory");
}
__device__ __forceinline__ void cp_commit() {
    asm volatile("cp.async.commit_group;\n" ::: "memory");
}
__device__ __forceinline__ void mma_tf32(float* c, const uint32_t* a, const uint32_t* b) {
    asm volatile(
        "mma.sync.aligned.m16n8k8.row.col.f32.tf32.tf32.f32 "
        "{%0,%1,%2,%3}, {%4,%5,%6,%7}, {%8,%9}, {%0,%1,%2,%3};"
        : "+f"(c[0]), "+f"(c[1]), "+f"(c[2]), "+f"(c[3])
        : "r"(a[0]), "r"(a[1]), "r"(a[2]), "r"(a[3]), "r"(b[0]), "r"(b[1]));
}

// =============================================================================
// tf32 GEMM with optional split-K batching and cross-iteration fragment pipeline.
// =============================================================================
template <int KB, int SPLITK, bool RND_A, bool RND_B>
__global__ void __launch_bounds__(NTHREADS, 2)
gemm_tf32_ker(const float* __restrict__ Ag, const float* __restrict__ Bg,
              float* __restrict__ Cg,
              int lda, int ldb, int ldc,
              size_t a_batch_stride, size_t b_batch_stride, size_t c_batch_stride) {
    extern __shared__ float sm[];

    const int tid  = threadIdx.x;
    const int lane = tid & 31;
    const int warp = tid >> 5;
    const int g = lane >> 2;          // 0..7
    const int q = lane & 3;           // 0..3
    const int wm = warp & 1;          // warp m index (2)
    const int wn = warp >> 1;         // warp n index (2)

    const int bz = blockIdx.z;
    const int zo = bz / SPLITK;
    const int ks_slice = bz % SPLITK;

    const float* A = Ag + (size_t)zo * a_batch_stride
                        + (size_t)ks_slice * KB * BK
                        + (size_t)blockIdx.y * BM * lda;
    const float* B = Bg + (size_t)zo * b_batch_stride
                        + (size_t)ks_slice * KB * BK * ldb
                        + (size_t)blockIdx.x * BN;
    float*       C = Cg + (size_t)bz * c_batch_stride
                        + (size_t)blockIdx.y * BM * ldc + (size_t)blockIdx.x * BN;

    const uint32_t smem0 = smem_u32(sm);

    // ---- gmem -> smem geometry (16B chunks, 128 threads: 8 A + 8 B chunks each) ----
    const int ar = tid >> 3;            // A base row (0..15), +16*i
    const int ac = (tid & 7) * 4;       // A float col
    const int br = tid >> 5;            // B base row (0..3), +4*i
    const int bc = (tid & 31) * 4;      // B float col

    auto load_stage = [&](int slot, int kb) {
        uint32_t sa = smem0 + (uint32_t)slot * (STG_FLOATS * 4);
        uint32_t sb = sa + A_STG_FLOATS * 4;
        const float* Ak = A + (size_t)kb * BK;
        const float* Bk = B + (size_t)kb * BK * ldb;
        #pragma unroll
        for (int i = 0; i < 8; i++) {
            int r = ar + 16 * i;
            cp16(sa + (uint32_t)(r * LDA_S + ac) * 4u, Ak + (size_t)r * lda + ac);
        }
        #pragma unroll
        for (int i = 0; i < 8; i++) {
            int r = br + 4 * i;
            cp16(sb + (uint32_t)(r * LDB_S + bc) * 4u, Bk + (size_t)r * ldb + bc);
        }
        cp_commit();
    };

    // ---- accumulators: 4 m-tiles x 8 n-tiles x 4 ----
    float c[4][8][4];
    #pragma unroll
    for (int mt = 0; mt < 4; mt++)
        #pragma unroll
        for (int nt = 0; nt < 8; nt++)
            #pragma unroll
            for (int i = 0; i < 4; i++) c[mt][nt][i] = 0.0f;

    // fragment double buffers
    uint32_t afr[2][4][4];
    uint32_t bfr[2][8][2];

    auto load_frags = [&](const uint32_t* As, const uint32_t* Bs, int ks, int buf) {
        #pragma unroll
        for (int mt = 0; mt < 4; mt++) {
            int r0 = wm * 64 + mt * 16 + g;
            int c0 = ks * 8 + q;
            uint32_t v0 = As[r0 * LDA_S + c0];
            uint32_t v1 = As[(r0 + 8) * LDA_S + c0];
            uint32_t v2 = As[r0 * LDA_S + c0 + 4];
            uint32_t v3 = As[(r0 + 8) * LDA_S + c0 + 4];
            if (RND_A) { v0 = rna_tf32_u(v0); v1 = rna_tf32_u(v1);
                         v2 = rna_tf32_u(v2); v3 = rna_tf32_u(v3); }
            afr[buf][mt][0] = v0; afr[buf][mt][1] = v1;
            afr[buf][mt][2] = v2; afr[buf][mt][3] = v3;
        }
        #pragma unroll
        for (int nt = 0; nt < 8; nt++) {
            int col = wn * 64 + nt * 8 + g;
            int r0 = ks * 8 + q;
            uint32_t v0 = Bs[r0 * LDB_S + col];
            uint32_t v1 = Bs[(r0 + 4) * LDB_S + col];
            if (RND_B) { v0 = rna_tf32_u(v0); v1 = rna_tf32_u(v1); }
            bfr[buf][nt][0] = v0; bfr[buf][nt][1] = v1;
        }
    };

    auto mma_batch = [&](int buf) {
        #pragma unroll
        for (int mt = 0; mt < 4; mt++)
            #pragma unroll
            for (int nt = 0; nt < 8; nt++)
                mma_tf32(c[mt][nt], afr[buf][mt], bfr[buf][nt]);
    };

    // ---- prologue: stages 0,1 in flight; frags(kb=0, ks=0) resident ----
    load_stage(0, 0);
    load_stage(1, 1);
    asm volatile("cp.async.wait_group 1;\n" ::: "memory");   // stage 0 done
    __syncthreads();
    {
        const uint32_t* As0 = reinterpret_cast<const uint32_t*>(sm);
        load_frags(As0, As0 + A_STG_FLOATS, 0, 0);
    }

    int slot_c = 0, slot_p = 2;

    // ---- main loop: barrier + stage maintenance at the ks2/ks3 seam ----
    #pragma unroll 1
    for (int kb = 0; kb < KB; ++kb) {
        const uint32_t* As = reinterpret_cast<const uint32_t*>(sm + slot_c * STG_FLOATS);
        const uint32_t* Bs = As + A_STG_FLOATS;

        load_frags(As, Bs, 1, 1);
        mma_batch(0);
        load_frags(As, Bs, 2, 0);
        mma_batch(1);
        load_frags(As, Bs, 3, 1);
        mma_batch(0);

        // stage maintenance (overlaps ks2/ks3 MMA drain)
        asm volatile("cp.async.wait_group 0;\n" ::: "memory");  // stage kb+1 landed
        __syncthreads();                                        // visible; slot kb-1 free
        int pf = kb + NSTAGE - 1;
        if (pf < KB) load_stage(slot_p, pf);
        if (++slot_p == NSTAGE) slot_p = 0;

        int slot_n = (slot_c + 1 == NSTAGE) ? 0 : slot_c + 1;
        if (kb + 1 < KB) {
            const uint32_t* An = reinterpret_cast<const uint32_t*>(sm + slot_n * STG_FLOATS);
            load_frags(An, An + A_STG_FLOATS, 0, 0);            // next kb ks0 prefetch
        }
        mma_batch(1);
        slot_c = slot_n;
    }

    // ---- epilogue ----
    #pragma unroll
    for (int mt = 0; mt < 4; mt++) {
        #pragma unroll
        for (int nt = 0; nt < 8; nt++) {
            int r0  = wm * 64 + mt * 16 + g;
            int col = wn * 64 + nt * 8 + 2 * q;
            float2 v0 = make_float2(c[mt][nt][0], c[mt][nt][1]);
            float2 v1 = make_float2(c[mt][nt][2], c[mt][nt][3]);
            *reinterpret_cast<float2*>(C + (size_t)r0 * ldc + col)       = v0;
            *reinterpret_cast<float2*>(C + (size_t)(r0 + 8) * ldc + col) = v1;
        }
    }
}

// ---- reduce E*SPLITK partials into g_wsum, rounding the sum to tf32 ----
__global__ void reduce_experts_ker() {
    size_t i = (size_t)blockIdx.x * blockDim.x + threadIdx.x;  // float4 index
    const float4* p = reinterpret_cast<const float4*>(g_part);
    float4 acc = p[i];
    #pragma unroll
    for (int e = 1; e < E_DIM * SPLITK_C; e++) {
        float4 v = p[(size_t)e * (H_DIM * H_DIM / 4) + i];
        acc.x += v.x; acc.y += v.y; acc.z += v.z; acc.w += v.w;
    }
    acc.x = rna_tf32(acc.x); acc.y = rna_tf32(acc.y);
    acc.z = rna_tf32(acc.z); acc.w = rna_tf32(acc.w);
    reinterpret_cast<float4*>(g_wsum)[i] = acc;
}

// ================= launch =================
extern "C" void kernel_launch(void* const* d_in, const int* in_sizes, int n_in,
                              void* d_out, int out_size) {
    const float* x  = (const float*)d_in[0];
    const float* w1 = (const float*)d_in[1];   // [E][H][N]
    const float* w2 = (const float*)d_in[2];   // [E][N][H]
    float* out = (float*)d_out;                // [A][M][H]

    float* part = nullptr; cudaGetSymbolAddress((void**)&part, g_part);
    float* wsum = nullptr; cudaGetSymbolAddress((void**)&wsum, g_wsum);

    constexpr int KB_C = (N_DIM / BK) / SPLITK_C;   // 32 kb-iters per combine CTA
    constexpr int KB_A = H_DIM / BK;                // 32 kb-iters for apply

    cudaFuncSetAttribute((const void*)gemm_tf32_ker<KB_C, SPLITK_C, true, true>,
                         cudaFuncAttributeMaxDynamicSharedMemorySize, SMEM_DYN);
    cudaFuncSetAttribute((const void*)gemm_tf32_ker<KB_A, 1, true, false>,
                         cudaFuncAttributeMaxDynamicSharedMemorySize, SMEM_DYN);

    // 1) per-expert, split-K combine: g_part[e][s] = rna(w1[e])_Ks @ rna(w2[e])_Ks
    gemm_tf32_ker<KB_C, SPLITK_C, true, true>
        <<<dim3(H_DIM / BN, H_DIM / BM, E_DIM * SPLITK_C), NTHREADS, SMEM_DYN>>>(
            w1, w2, part,
            N_DIM, H_DIM, H_DIM,
            (size_t)H_DIM * N_DIM, (size_t)N_DIM * H_DIM, (size_t)H_DIM * H_DIM);

    // 2) reduce E*SPLITK partials (+ tf32 rounding of the sum)
    reduce_experts_ker<<<(H_DIM * H_DIM / 4) / 256, 256>>>();

    // 3) apply: out = rna(x) @ W   (W pre-rounded by reduce)
    gemm_tf32_ker<KB_A, 1, true, false>
        <<<dim3(H_DIM / BN, (A_DIM * M_DIM) / BM, 1), NTHREADS, SMEM_DYN>>>(
            x, wsum, out,
            H_DIM, H_DIM, H_DIM,
            0, 0, 0);
}